// round 2
// baseline (speedup 1.0000x reference)
#include <cuda_runtime.h>
#include <cstdint>

// Problem constants: N=200000 nodes, D=256 features, G=512 graphs.
#define D 256
#define G 512
#define MAX_N 262144
#define MAX_NB 1024
#define GPB 16                 // graphs per block in the GEMM

__device__ int   g_idx[MAX_N];
__device__ int   g_flags[MAX_NB];
__device__ float g_sum[G * D];
__device__ float g_hG[G * D];

// ---------------------------------------------------------------------------
// Kernel 1: detect int64 vs int32 storage of batch_idx (see R0 notes) and
// zero the segment accumulator in the same launch.
// ---------------------------------------------------------------------------
__global__ void k_detect(const int* __restrict__ raw, int n)
{
    int i = blockIdx.x * blockDim.x + threadIdx.x;
    int odd_nz = 0, even_nz = 0;
    if (i < n) {
        int v = raw[i];
        if (v != 0) {
            if (i & 1) odd_nz = 1; else even_nz = 1;
        }
    }
    int o = __syncthreads_or(odd_nz);
    int e = __syncthreads_or(even_nz);
    if (threadIdx.x == 0) g_flags[blockIdx.x] = o | (e << 1);
    if (i < G * D) g_sum[i] = 0.0f;
}

// ---------------------------------------------------------------------------
// Kernel 2: reduce flags, normalize indices to int32.
// ---------------------------------------------------------------------------
__global__ void k_convert(const int* __restrict__ raw, int n, int nb)
{
    int f = 0;
    for (int j = threadIdx.x; j < nb; j += blockDim.x) f |= g_flags[j];
    f = __syncthreads_or(f);
    int any_odd  = f & 1;
    int any_even = (f >> 1) & 1;

    int i = blockIdx.x * blockDim.x + threadIdx.x;
    if (i < n) {
        int v;
        if (any_odd)       v = raw[i];       // int32 data
        else if (any_even) v = raw[2 * i];   // int64 data, low word
        else               v = 0;
        g_idx[i] = v;
    }
}

// ---------------------------------------------------------------------------
// Kernel 3: segment sum over sorted batch_idx. Block owns 256 contiguous
// rows; 64 column-quads x 4 row-stripes; register accumulation, atomic
// flush only on segment boundary. Streaming loads for h (touched once).
// ---------------------------------------------------------------------------
__global__ void k_segsum(const float* __restrict__ h, int n)
{
    __shared__ int sidx[256];
    int r0 = blockIdx.x * 256;
    {
        int r = r0 + threadIdx.x;
        sidx[threadIdx.x] = (r < n) ? g_idx[r] : -1;
    }
    __syncthreads();

    int tx = threadIdx.x & 63;
    int ty = threadIdx.x >> 6;

    float4 acc = make_float4(0.f, 0.f, 0.f, 0.f);
    int cur = -1;

    for (int rr = ty; rr < 256; rr += 4) {
        int row = r0 + rr;
        if (row >= n) break;
        int seg = sidx[rr];
        if (seg != cur) {
            if (cur >= 0) {
                float* dst = &g_sum[cur * D + tx * 4];
                atomicAdd(dst + 0, acc.x);
                atomicAdd(dst + 1, acc.y);
                atomicAdd(dst + 2, acc.z);
                atomicAdd(dst + 3, acc.w);
            }
            acc = make_float4(0.f, 0.f, 0.f, 0.f);
            cur = seg;
        }
        const float4 v = __ldcs(reinterpret_cast<const float4*>(h + (size_t)row * D + tx * 4));
        acc.x += v.x; acc.y += v.y; acc.z += v.z; acc.w += v.w;
    }
    if (cur >= 0) {
        float* dst = &g_sum[cur * D + tx * 4];
        atomicAdd(dst + 0, acc.x);
        atomicAdd(dst + 1, acc.y);
        atomicAdd(dst + 2, acc.z);
        atomicAdd(dst + 3, acc.w);
    }
}

// ---------------------------------------------------------------------------
// Kernel 4: h_G = relu(sum @ W + b), tiled GPB graphs per block so W is
// read only G/GPB times total (8 MB of L2 traffic instead of 128 MB).
// Thread t owns output column t for all GPB graphs.
// ---------------------------------------------------------------------------
__global__ void __launch_bounds__(256) k_gemm(const float* __restrict__ W,
                                              const float* __restrict__ b)
{
    __shared__ float s[GPB][D];
    int g0 = blockIdx.x * GPB;
    int t  = threadIdx.x;

    // load GPB pooled rows into smem
    for (int r = 0; r < GPB; r++)
        s[r][t] = g_sum[(g0 + r) * D + t];
    __syncthreads();

    float bias = b[t];
    float acc[GPB];
#pragma unroll
    for (int r = 0; r < GPB; r++) acc[r] = bias;

#pragma unroll 4
    for (int k = 0; k < D; k++) {
        float w = W[k * D + t];
#pragma unroll
        for (int r = 0; r < GPB; r++)
            acc[r] = fmaf(s[r][k], w, acc[r]);
    }

#pragma unroll
    for (int r = 0; r < GPB; r++)
        g_hG[(g0 + r) * D + t] = fmaxf(acc[r], 0.0f);
}

// ---------------------------------------------------------------------------
// Kernel 5: out = h_G[batch_idx] + h. Streaming load h / store out
// (evict-first) so they don't thrash L2; g_hG (512 KB) stays L2-resident.
// ---------------------------------------------------------------------------
__global__ void k_out(const float* __restrict__ h, float* __restrict__ out, int n)
{
    int gt = blockIdx.x * blockDim.x + threadIdx.x;
    int i = gt >> 6;
    int q = gt & 63;
    if (i >= n) return;
    int seg = g_idx[i];
    const float4 a = __ldcs(reinterpret_cast<const float4*>(h + (size_t)i * D + q * 4));
    const float4 v = *reinterpret_cast<const float4*>(g_hG + seg * D + q * 4);
    float4 r;
    r.x = a.x + v.x; r.y = a.y + v.y; r.z = a.z + v.z; r.w = a.w + v.w;
    __stcs(reinterpret_cast<float4*>(out + (size_t)i * D + q * 4), r);
}

extern "C" void kernel_launch(void* const* d_in, const int* in_sizes, int n_in,
                              void* d_out, int out_size)
{
    const float* h   = (const float*)d_in[0];
    const int*   raw = (const int*)  d_in[1];
    const float* W   = (const float*)d_in[2];
    const float* b   = (const float*)d_in[3];
    float* out = (float*)d_out;

    const int n  = in_sizes[1];
    const int nb = (n + 255) / 256;

    k_detect <<<nb, 256>>>(raw, n);
    k_convert<<<nb, 256>>>(raw, n, nb);
    k_segsum <<<nb, 256>>>(h, n);
    k_gemm   <<<G / GPB, 256>>>(W, b);
    {
        long long tq = (long long)n * 64;
        int blocks = (int)((tq + 255) / 256);
        k_out<<<blocks, 256>>>(h, out, n);
    }
}

// round 3
// speedup vs baseline: 1.2161x; 1.2161x over previous
#include <cuda_runtime.h>
#include <cstdint>

// Problem constants: N=200000 nodes, D=256 features, G=512 graphs.
#define D 256
#define G 512
#define MAX_N 262144
#define MAX_NB 1024
#define GPB 16                 // graphs per block-tile in GEMM
#define KPB 16                 // k-values per block-slice in GEMM

__device__ int   g_idx[MAX_N];
__device__ int   g_flags[MAX_NB];
__device__ float g_sum[G * D];     // pooled features
__device__ float g_acc[G * D];     // split-K GEMM accumulator (pre-bias, pre-relu)

// ---------------------------------------------------------------------------
// Kernel 1: detect int64 vs int32 storage of batch_idx, and zero both
// accumulators (must re-zero every graph replay).
// ---------------------------------------------------------------------------
__global__ void k_detect(const int* __restrict__ raw, int n)
{
    int i = blockIdx.x * blockDim.x + threadIdx.x;
    int odd_nz = 0, even_nz = 0;
    if (i < n) {
        int v = raw[i];
        if (v != 0) {
            if (i & 1) odd_nz = 1; else even_nz = 1;
        }
    }
    int o = __syncthreads_or(odd_nz);
    int e = __syncthreads_or(even_nz);
    if (threadIdx.x == 0) g_flags[blockIdx.x] = o | (e << 1);
    if (i < G * D) { g_sum[i] = 0.0f; g_acc[i] = 0.0f; }
}

// ---------------------------------------------------------------------------
// Kernel 2: reduce flags, normalize indices to int32.
// ---------------------------------------------------------------------------
__global__ void k_convert(const int* __restrict__ raw, int n, int nb)
{
    int f = 0;
    for (int j = threadIdx.x; j < nb; j += blockDim.x) f |= g_flags[j];
    f = __syncthreads_or(f);
    int any_odd  = f & 1;
    int any_even = (f >> 1) & 1;

    int i = blockIdx.x * blockDim.x + threadIdx.x;
    if (i < n) {
        int v;
        if (any_odd)       v = raw[i];       // int32 data
        else if (any_even) v = raw[2 * i];   // int64 data, low word
        else               v = 0;
        g_idx[i] = v;
    }
}

// ---------------------------------------------------------------------------
// Kernel 3: segment sum over sorted batch_idx. Block owns 256 contiguous
// rows; 64 column-quads x 4 row-stripes; register accumulation, atomic
// flush only on segment boundary. Streaming loads for h (touched once).
// ---------------------------------------------------------------------------
__global__ void k_segsum(const float* __restrict__ h, int n)
{
    __shared__ int sidx[256];
    int r0 = blockIdx.x * 256;
    {
        int r = r0 + threadIdx.x;
        sidx[threadIdx.x] = (r < n) ? g_idx[r] : -1;
    }
    __syncthreads();

    int tx = threadIdx.x & 63;
    int ty = threadIdx.x >> 6;

    float4 acc = make_float4(0.f, 0.f, 0.f, 0.f);
    int cur = -1;

    for (int rr = ty; rr < 256; rr += 4) {
        int row = r0 + rr;
        if (row >= n) break;
        int seg = sidx[rr];
        if (seg != cur) {
            if (cur >= 0) {
                float* dst = &g_sum[cur * D + tx * 4];
                atomicAdd(dst + 0, acc.x);
                atomicAdd(dst + 1, acc.y);
                atomicAdd(dst + 2, acc.z);
                atomicAdd(dst + 3, acc.w);
            }
            acc = make_float4(0.f, 0.f, 0.f, 0.f);
            cur = seg;
        }
        const float4 v = __ldcs(reinterpret_cast<const float4*>(h + (size_t)row * D + tx * 4));
        acc.x += v.x; acc.y += v.y; acc.z += v.z; acc.w += v.w;
    }
    if (cur >= 0) {
        float* dst = &g_sum[cur * D + tx * 4];
        atomicAdd(dst + 0, acc.x);
        atomicAdd(dst + 1, acc.y);
        atomicAdd(dst + 2, acc.z);
        atomicAdd(dst + 3, acc.w);
    }
}

// ---------------------------------------------------------------------------
// Kernel 4: split-K GEMM. grid = (G/GPB, D/KPB) = (32, 16) = 512 blocks.
// Block (gx, ky): graphs [gx*GPB, +GPB), k-range [ky*KPB, +KPB).
// Each thread owns output column t for GPB graphs over KPB k's, then
// atomically accumulates into g_acc. W slice per block = 16 KB; total W
// traffic = 8 MB. Full-chip parallelism (512 blocks).
// ---------------------------------------------------------------------------
__global__ void __launch_bounds__(256) k_gemm_splitk(const float* __restrict__ W)
{
    __shared__ float s[GPB][KPB];   // pooled values for this (graph-tile, k-slice)
    int g0 = blockIdx.x * GPB;
    int k0 = blockIdx.y * KPB;
    int t  = threadIdx.x;

    // 256 threads load exactly GPB*KPB = 256 pooled values
    {
        int r  = t >> 4;       // graph within tile
        int kk = t & 15;       // k within slice
        s[r][kk] = g_sum[(g0 + r) * D + (k0 + kk)];
    }
    __syncthreads();

    float acc[GPB];
#pragma unroll
    for (int r = 0; r < GPB; r++) acc[r] = 0.0f;

#pragma unroll
    for (int kk = 0; kk < KPB; kk++) {
        float w = W[(k0 + kk) * D + t];
#pragma unroll
        for (int r = 0; r < GPB; r++)
            acc[r] = fmaf(s[r][kk], w, acc[r]);
    }

#pragma unroll
    for (int r = 0; r < GPB; r++)
        atomicAdd(&g_acc[(g0 + r) * D + t], acc[r]);
}

// ---------------------------------------------------------------------------
// Kernel 5: out = relu(g_acc[seg] + b) + h. Bias+ReLU fused here (free ALU
// on a memory-bound kernel; b and g_acc are L2-resident). Streaming
// load/store for the 410 MB h/out traffic.
// ---------------------------------------------------------------------------
__global__ void k_out(const float* __restrict__ h, const float* __restrict__ b,
                      float* __restrict__ out, int n)
{
    int gt = blockIdx.x * blockDim.x + threadIdx.x;
    int i = gt >> 6;
    int q = gt & 63;
    if (i >= n) return;
    int seg = g_idx[i];
    const float4 a  = __ldcs(reinterpret_cast<const float4*>(h + (size_t)i * D + q * 4));
    const float4 v  = *reinterpret_cast<const float4*>(g_acc + seg * D + q * 4);
    const float4 bb = *reinterpret_cast<const float4*>(b + q * 4);
    float4 r;
    r.x = fmaxf(v.x + bb.x, 0.0f) + a.x;
    r.y = fmaxf(v.y + bb.y, 0.0f) + a.y;
    r.z = fmaxf(v.z + bb.z, 0.0f) + a.z;
    r.w = fmaxf(v.w + bb.w, 0.0f) + a.w;
    __stcs(reinterpret_cast<float4*>(out + (size_t)i * D + q * 4), r);
}

extern "C" void kernel_launch(void* const* d_in, const int* in_sizes, int n_in,
                              void* d_out, int out_size)
{
    const float* h   = (const float*)d_in[0];
    const int*   raw = (const int*)  d_in[1];
    const float* W   = (const float*)d_in[2];
    const float* b   = (const float*)d_in[3];
    float* out = (float*)d_out;

    const int n  = in_sizes[1];
    const int nb = (n + 255) / 256;

    k_detect <<<nb, 256>>>(raw, n);
    k_convert<<<nb, 256>>>(raw, n, nb);
    k_segsum <<<nb, 256>>>(h, n);
    k_gemm_splitk<<<dim3(G / GPB, D / KPB), 256>>>(W);
    {
        long long tq = (long long)n * 64;
        int blocks = (int)((tq + 255) / 256);
        k_out<<<blocks, 256>>>(h, b, out, n);
    }
}

// round 4
// speedup vs baseline: 1.2228x; 1.0056x over previous
#include <cuda_runtime.h>
#include <cstdint>

// Problem constants: N=200000 nodes, D=256 features, G=512 graphs.
#define D 256
#define G 512
#define MAX_NB 1024
#define GPB 16                 // graphs per block-tile in GEMM
#define KPB 16                 // k-values per block-slice in GEMM

__device__ int   g_flags[MAX_NB];
__device__ int   g_layout;         // 0 = int32 indices, 1 = int64 indices
__device__ float g_sum[G * D];     // pooled features
__device__ float g_acc[G * D];     // split-K GEMM accumulator (pre-bias, pre-relu)

// Fetch node i's graph index given storage layout.
__device__ __forceinline__ int load_idx(const int* __restrict__ raw, int i, int layout)
{
    return layout ? raw[2 * i] : raw[i];
}

// ---------------------------------------------------------------------------
// Kernel 1: detect int64 vs int32 storage of batch_idx (little-endian int64
// values < 512 have all odd words zero; sorted nonzero int32 data has
// nonzero odd words). Also zeros both small accumulators (must re-zero
// every graph replay).
// ---------------------------------------------------------------------------
__global__ void k_detect(const int* __restrict__ raw, int n)
{
    int i = blockIdx.x * blockDim.x + threadIdx.x;
    int odd_nz = 0, even_nz = 0;
    if (i < n) {
        int v = raw[i];
        if (v != 0) {
            if (i & 1) odd_nz = 1; else even_nz = 1;
        }
    }
    int o = __syncthreads_or(odd_nz);
    int e = __syncthreads_or(even_nz);
    if (threadIdx.x == 0) g_flags[blockIdx.x] = o | (e << 1);
    if (i < G * D) { g_sum[i] = 0.0f; g_acc[i] = 0.0f; }
}

// ---------------------------------------------------------------------------
// Kernel 2: reduce per-block flags into a single layout decision.
// any_odd  -> int32; else any_even -> int64; else (all zero) -> int32
// (in-bounds and correct under both layouts).
// ---------------------------------------------------------------------------
__global__ void k_flag(int nb)
{
    int f = 0;
    for (int j = threadIdx.x; j < nb; j += blockDim.x) f |= g_flags[j];
    f = __syncthreads_or(f);
    if (threadIdx.x == 0)
        g_layout = (f & 1) ? 0 : ((f & 2) ? 1 : 0);
}

// ---------------------------------------------------------------------------
// Kernel 3: segment sum over sorted batch_idx. Block owns 256 contiguous
// rows; 64 column-quads x 4 row-stripes; register accumulation, atomic
// flush only on segment boundary. Indices read directly from raw buffer.
// ---------------------------------------------------------------------------
__global__ void k_segsum(const float* __restrict__ h, const int* __restrict__ raw, int n)
{
    __shared__ int sidx[256];
    int layout = g_layout;
    int r0 = blockIdx.x * 256;
    {
        int r = r0 + threadIdx.x;
        sidx[threadIdx.x] = (r < n) ? load_idx(raw, r, layout) : -1;
    }
    __syncthreads();

    int tx = threadIdx.x & 63;
    int ty = threadIdx.x >> 6;

    float4 acc = make_float4(0.f, 0.f, 0.f, 0.f);
    int cur = -1;

    for (int rr = ty; rr < 256; rr += 4) {
        int row = r0 + rr;
        if (row >= n) break;
        int seg = sidx[rr];
        if (seg != cur) {
            if (cur >= 0) {
                float* dst = &g_sum[cur * D + tx * 4];
                atomicAdd(dst + 0, acc.x);
                atomicAdd(dst + 1, acc.y);
                atomicAdd(dst + 2, acc.z);
                atomicAdd(dst + 3, acc.w);
            }
            acc = make_float4(0.f, 0.f, 0.f, 0.f);
            cur = seg;
        }
        const float4 v = __ldcs(reinterpret_cast<const float4*>(h + (size_t)row * D + tx * 4));
        acc.x += v.x; acc.y += v.y; acc.z += v.z; acc.w += v.w;
    }
    if (cur >= 0) {
        float* dst = &g_sum[cur * D + tx * 4];
        atomicAdd(dst + 0, acc.x);
        atomicAdd(dst + 1, acc.y);
        atomicAdd(dst + 2, acc.z);
        atomicAdd(dst + 3, acc.w);
    }
}

// ---------------------------------------------------------------------------
// Kernel 4: split-K GEMM. grid = (G/GPB, D/KPB) = (32, 16) = 512 blocks.
// W loads batched into registers first (MLP) then FMA chains, then spread
// atomic accumulate into g_acc.
// ---------------------------------------------------------------------------
__global__ void __launch_bounds__(256) k_gemm_splitk(const float* __restrict__ W)
{
    __shared__ float s[GPB][KPB];
    int g0 = blockIdx.x * GPB;
    int k0 = blockIdx.y * KPB;
    int t  = threadIdx.x;

    // batch-issue the KPB W loads up front
    float w[KPB];
#pragma unroll
    for (int kk = 0; kk < KPB; kk++)
        w[kk] = __ldg(&W[(k0 + kk) * D + t]);

    {
        int r  = t >> 4;
        int kk = t & 15;
        s[r][kk] = g_sum[(g0 + r) * D + (k0 + kk)];
    }
    __syncthreads();

    float acc[GPB];
#pragma unroll
    for (int r = 0; r < GPB; r++) acc[r] = 0.0f;

#pragma unroll
    for (int kk = 0; kk < KPB; kk++) {
#pragma unroll
        for (int r = 0; r < GPB; r++)
            acc[r] = fmaf(s[r][kk], w[kk], acc[r]);
    }

#pragma unroll
    for (int r = 0; r < GPB; r++)
        atomicAdd(&g_acc[(g0 + r) * D + t], acc[r]);
}

// ---------------------------------------------------------------------------
// Kernel 5: out = relu(g_acc[seg] + b) + h. Two float4 quads per thread
// (front-batched loads for MLP). Indices read directly from raw buffer.
// ---------------------------------------------------------------------------
__global__ void k_out(const float* __restrict__ h, const int* __restrict__ raw,
                      const float* __restrict__ b, float* __restrict__ out, int n)
{
    int layout = g_layout;
    int gt = blockIdx.x * blockDim.x + threadIdx.x;   // one thread per 2 quads
    int i = gt >> 5;          // row
    int q = (gt & 31) * 2;    // first of two column quads
    if (i >= n) return;
    int seg = load_idx(raw, i, layout);

    const float4* hp = reinterpret_cast<const float4*>(h + (size_t)i * D) + q;
    const float4 a0 = __ldcs(hp);
    const float4 a1 = __ldcs(hp + 1);
    const float4* vp = reinterpret_cast<const float4*>(g_acc + seg * D) + q;
    const float4 v0 = vp[0];
    const float4 v1 = vp[1];
    const float4* bp = reinterpret_cast<const float4*>(b) + q;
    const float4 b0 = bp[0];
    const float4 b1 = bp[1];

    float4 r0, r1;
    r0.x = fmaxf(v0.x + b0.x, 0.0f) + a0.x;
    r0.y = fmaxf(v0.y + b0.y, 0.0f) + a0.y;
    r0.z = fmaxf(v0.z + b0.z, 0.0f) + a0.z;
    r0.w = fmaxf(v0.w + b0.w, 0.0f) + a0.w;
    r1.x = fmaxf(v1.x + b1.x, 0.0f) + a1.x;
    r1.y = fmaxf(v1.y + b1.y, 0.0f) + a1.y;
    r1.z = fmaxf(v1.z + b1.z, 0.0f) + a1.z;
    r1.w = fmaxf(v1.w + b1.w, 0.0f) + a1.w;

    float4* op = reinterpret_cast<float4*>(out + (size_t)i * D) + q;
    __stcs(op, r0);
    __stcs(op + 1, r1);
}

extern "C" void kernel_launch(void* const* d_in, const int* in_sizes, int n_in,
                              void* d_out, int out_size)
{
    const float* h   = (const float*)d_in[0];
    const int*   raw = (const int*)  d_in[1];
    const float* W   = (const float*)d_in[2];
    const float* b   = (const float*)d_in[3];
    float* out = (float*)d_out;

    const int n  = in_sizes[1];
    const int nb = (n + 255) / 256;

    k_detect<<<nb, 256>>>(raw, n);
    k_flag  <<<1, 256>>>(nb);
    k_segsum<<<nb, 256>>>(h, raw, n);
    k_gemm_splitk<<<dim3(G / GPB, D / KPB), 256>>>(W);
    {
        long long tt = (long long)n * 32;   // one thread per 2 float4
        int blocks = (int)((tt + 255) / 256);
        k_out<<<blocks, 256>>>(h, raw, b, out, n);
    }
}